// round 6
// baseline (speedup 1.0000x reference)
#include <cuda_runtime.h>
#include <cuda_bf16.h>
#include <math.h>
#include <stdint.h>

#define TT 512
#define BB 256
#define DIN 256
#define DLT 256
#define NPERSIST 128
#define NGRP 16

// output layout (floats): H[(T+1),B,DL], C[(T+1),B,DL], F[T,B,DL], I[T,B,DL], O[T,B,DL]
#define H_OFF 0
#define C_OFF ((TT + 1) * BB * DLT)
#define F_OFF (2 * (TT + 1) * BB * DLT)
#define I_OFF (F_OFF + TT * BB * DLT)
#define O_OFF (I_OFF + TT * BB * DLT)

// persist smem layout (byte offsets into dynamic smem)
#define PWS 264
#define WSH_B 0                      // 64 x 264 x 2      = 33792
#define WSL_B 33792
#define HSH_B 67584                  // 32 x 264 x 2      = 16896
#define HSL_B 84480
#define SG_B  101376                 // 4*32*18 floats    = 9216
#define CS_B  110592                 // 512 floats        = 2048
#define PSMEM 112640

// phase1 smem layout (byte offsets, same dynamic buffer)
#define P1S 40
#define AH_B 0                       // 128 x 40 x 2 = 10240
#define AL_B 10240
#define BH_B 20480
#define BL_B 30720

// bf16 hi/lo scratch for X and x-side weights
__device__ __nv_bfloat16 g_Xhi[TT * BB * DIN];
__device__ __nv_bfloat16 g_Xlo[TT * BB * DIN];
__device__ __nv_bfloat16 g_Wxhi[4 * DLT * DIN];
__device__ __nv_bfloat16 g_Wxlo[4 * DLT * DIN];

// per-t completion counters (phase1 -> persist), reset each call by convX
__device__ unsigned int t_done[TT];
// per-group barrier state, 128B-separated
__device__ unsigned int g_cnt2[8 * 32];
__device__ unsigned int g_gen2[8 * 32];

__device__ __forceinline__ float sigm(float x) { return 1.0f / (1.0f + __expf(-x)); }
__device__ __forceinline__ float tanhfast(float x) { return 1.0f - 2.0f / (__expf(2.0f * x) + 1.0f); }

__device__ __forceinline__ unsigned int ld_acquire_gpu(const unsigned int* p)
{
    unsigned int v;
    asm volatile("ld.acquire.gpu.global.u32 %0, [%1];" : "=r"(v) : "l"(p) : "memory");
    return v;
}
__device__ __forceinline__ void red_release_add(unsigned int* p, unsigned int v)
{
    asm volatile("red.release.gpu.global.add.u32 [%0], %1;" :: "l"(p), "r"(v) : "memory");
}

__device__ __forceinline__ void split2(float x, float y, uint32_t& hi, uint32_t& lo)
{
    __nv_bfloat16 hx = __float2bfloat16(x);
    __nv_bfloat16 hy = __float2bfloat16(y);
    __nv_bfloat16 lx = __float2bfloat16(x - __bfloat162float(hx));
    __nv_bfloat16 ly = __float2bfloat16(y - __bfloat162float(hy));
    __nv_bfloat162 h2 = __halves2bfloat162(hx, hy);
    __nv_bfloat162 l2 = __halves2bfloat162(lx, ly);
    hi = *(uint32_t*)&h2;
    lo = *(uint32_t*)&l2;
}

__device__ __forceinline__ void mma16816(float* d, const uint32_t* a, const uint32_t* b)
{
    asm volatile(
        "mma.sync.aligned.m16n8k16.row.col.f32.bf16.bf16.f32 "
        "{%0,%1,%2,%3}, {%4,%5,%6,%7}, {%8,%9}, {%0,%1,%2,%3};"
        : "+f"(d[0]), "+f"(d[1]), "+f"(d[2]), "+f"(d[3])
        : "r"(a[0]), "r"(a[1]), "r"(a[2]), "r"(a[3]), "r"(b[0]), "r"(b[1]));
}

__device__ __forceinline__ void ldsm4(uint32_t* r, uint32_t addr)
{
    asm volatile("ldmatrix.sync.aligned.m8n8.x4.shared.b16 {%0,%1,%2,%3}, [%4];"
                 : "=r"(r[0]), "=r"(r[1]), "=r"(r[2]), "=r"(r[3]) : "r"(addr));
}

// ---------------------------------------------------------------------------
// converters (also reset t_done)
// ---------------------------------------------------------------------------
__global__ void __launch_bounds__(256) convX_kernel(const float* __restrict__ X)
{
    if (blockIdx.x < 2) t_done[blockIdx.x * 256 + threadIdx.x] = 0;
    int idx = blockIdx.x * 256 + threadIdx.x;
    if (idx < TT * BB * DIN / 4) {
        float4 v = *(const float4*)&X[(size_t)idx * 4];
        uint32_t h01, l01, h23, l23;
        split2(v.x, v.y, h01, l01);
        split2(v.z, v.w, h23, l23);
        ((uint2*)g_Xhi)[idx] = make_uint2(h01, h23);
        ((uint2*)g_Xlo)[idx] = make_uint2(l01, l23);
    }
}

__global__ void __launch_bounds__(256) convW_kernel(
    const float* __restrict__ W0, const float* __restrict__ W1,
    const float* __restrict__ W2, const float* __restrict__ W3)
{
    int idx = blockIdx.x * 256 + threadIdx.x;      // float4 index, 65536 total
    int g = idx >> 14;
    int j = (idx >> 6) & 255;
    int q = idx & 63;
    const float* Wg = (g == 0) ? W0 : (g == 1) ? W1 : (g == 2) ? W2 : W3;
    float4 v = *(const float4*)&Wg[(size_t)j * 512 + 256 + q * 4];
    uint32_t h01, l01, h23, l23;
    split2(v.x, v.y, h01, l01);
    split2(v.z, v.w, h23, l23);
    int d2 = g * 16384 + j * 64 + q;
    ((uint2*)g_Wxhi)[d2] = make_uint2(h01, h23);
    ((uint2*)g_Wxlo)[d2] = make_uint2(l01, l23);
}

// ---------------------------------------------------------------------------
// merged kernel: blocks 0..127 persist recurrence, blocks 128..8319 phase1.
// ---------------------------------------------------------------------------
__global__ void __launch_bounds__(256, 2) fused_kernel(
    const float* __restrict__ W0, const float* __restrict__ W1,
    const float* __restrict__ W2, const float* __restrict__ W3,
    const float* __restrict__ b0v, const float* __restrict__ b1v,
    const float* __restrict__ b2v, const float* __restrict__ b3v,
    float* __restrict__ out)
{
    extern __shared__ char smem[];
    const int tid  = threadIdx.x;
    const int lane = tid & 31;
    const int warp = tid >> 5;
    const uint32_t shb = (uint32_t)__cvta_generic_to_shared(smem);
    const int rowsel = lane & 15;
    const int koff   = (lane >> 4) * 8;   // bf16 units

    if (blockIdx.x < NPERSIST) {
        // =================== persist role ===================
        __nv_bfloat16* wsH = (__nv_bfloat16*)(smem + WSH_B);
        __nv_bfloat16* wsL = (__nv_bfloat16*)(smem + WSL_B);
        __nv_bfloat16* hsH = (__nv_bfloat16*)(smem + HSH_B);
        __nv_bfloat16* hsL = (__nv_bfloat16*)(smem + HSL_B);
        float* sg = (float*)(smem + SG_B);
        float* cs = (float*)(smem + CS_B);

        const int bt = blockIdx.x >> 4;     // 0..7
        const int jt = blockIdx.x & 15;     // 0..15
        const int b0 = bt * 32;
        const int j0 = jt * 16;
        const int slot = bt * 32;

        __shared__ unsigned s_gen0;
        if (tid == 0) s_gen0 = ld_acquire_gpu(&g_gen2[slot]);

        // weight slice: 64 gc (4 gates x 16 j) x 256 k, split hi/lo
#pragma unroll
        for (int it = 0; it < 16; it++) {
            int idx = tid + it * 256;          // float4 idx 0..4095
            int gc = idx >> 6;
            int kq = idx & 63;
            int gg = gc >> 4;
            int jr = j0 + (gc & 15);
            const float* Wg = (gg == 0) ? W0 : (gg == 1) ? W1 : (gg == 2) ? W2 : W3;
            float4 v = *(const float4*)&Wg[(size_t)jr * 512 + kq * 4];
            uint32_t h01, l01, h23, l23;
            split2(v.x, v.y, h01, l01);
            split2(v.z, v.w, h23, l23);
            int base = gc * PWS + kq * 4;
            *(uint32_t*)&wsH[base]     = h01;
            *(uint32_t*)&wsH[base + 2] = h23;
            *(uint32_t*)&wsL[base]     = l01;
            *(uint32_t*)&wsL[base + 2] = l23;
        }

        // init: zero c state, H0/C0 tiles
        {
            int cell = tid * 2;
            int r  = cell >> 4;
            int jl = cell & 15;
            float2 z = make_float2(0.0f, 0.0f);
            *(float2*)&cs[cell] = z;
            *(float2*)&out[H_OFF + (b0 + r) * DLT + j0 + jl] = z;
            *(float2*)&out[C_OFF + (b0 + r) * DLT + j0 + jl] = z;
        }
        __syncthreads();
        const unsigned base_gen = s_gen0;

        // group barrier helper inline (16 CTAs of this b-group)
        // warp roles: wm = row half (16 rows), wg = gate
        const int wm = warp & 1;
        const int wg = warp >> 1;
        const int lg = lane >> 2;
        const int tq = lane & 3;

        const uint32_t aoffH = shb + HSH_B + ((wm * 16 + rowsel) * PWS + koff) * 2;
        const uint32_t boffH = shb + WSH_B + ((wg * 16 + rowsel) * PWS + koff) * 2;

        // initial group barrier
        {
            __syncthreads();
            if (tid == 0) {
                __threadfence();
                if (atomicAdd(&g_cnt2[slot], 1) == NGRP - 1) {
                    atomicExch(&g_cnt2[slot], 0);
                    red_release_add(&g_gen2[slot], 1);
                } else {
                    while (ld_acquire_gpu(&g_gen2[slot]) != base_gen + 1) { __nanosleep(32); }
                }
                __threadfence();
            }
            __syncthreads();
        }

        for (int t = 0; t < TT; t++) {
            // load + split h tile: 32 rows x 256 k
            const float* hsrc = out + H_OFF + t * (BB * DLT);
#pragma unroll
            for (int it = 0; it < 8; it++) {
                int idx = tid + it * 256;      // 0..2047 float4
                int br = idx >> 6;
                int kq = idx & 63;
                float4 v = *(const float4*)&hsrc[(b0 + br) * 256 + kq * 4];
                uint32_t h01, l01, h23, l23;
                split2(v.x, v.y, h01, l01);
                split2(v.z, v.w, h23, l23);
                int base = br * PWS + kq * 4;
                *(uint32_t*)&hsH[base]     = h01;
                *(uint32_t*)&hsH[base + 2] = h23;
                *(uint32_t*)&hsL[base]     = l01;
                *(uint32_t*)&hsL[base + 2] = l23;
            }
            // wait for phase1 stash for this t
            if (tid == 0) {
                while (ld_acquire_gpu(&t_done[t]) != 16u) { __nanosleep(128); }
            }
            __syncthreads();

            // prefetch stash (gate wg): rows wm*16+lg(+8), cols j0 + n8*8 + tq*2
            float2 zpre[2][2];
#pragma unroll
            for (int n8 = 0; n8 < 2; n8++) {
                int col = j0 + n8 * 8 + tq * 2;
#pragma unroll
                for (int h = 0; h < 2; h++) {
                    int mrow = t * BB + b0 + wm * 16 + lg + h * 8;
                    int stash;
                    if (wg == 0)      stash = F_OFF + mrow * DLT + col;
                    else if (wg == 1) stash = I_OFF + mrow * DLT + col;
                    else if (wg == 2) stash = C_OFF + (mrow + BB) * DLT + col;
                    else              stash = O_OFF + mrow * DLT + col;
                    zpre[n8][h] = *(const float2*)&out[stash];
                }
            }

            // mma: 16 rows x 16 gate-cols, 3-pass split, ldmatrix frags
            float acc[2][4];
#pragma unroll
            for (int j = 0; j < 2; j++)
#pragma unroll
                for (int u = 0; u < 4; u++) acc[j][u] = 0.0f;

#pragma unroll
            for (int k16 = 0; k16 < 256; k16 += 16) {
                uint32_t ah[4], al[4], b4h[4], b4l[4];
                ldsm4(ah,  aoffH + k16 * 2);
                ldsm4(al,  aoffH + (HSL_B - HSH_B) + k16 * 2);
                ldsm4(b4h, boffH + k16 * 2);
                ldsm4(b4l, boffH + (WSL_B - WSH_B) + k16 * 2);
                uint32_t bh0[2] = { b4h[0], b4h[2] };
                uint32_t bh1[2] = { b4h[1], b4h[3] };
                uint32_t bl0[2] = { b4l[0], b4l[2] };
                uint32_t bl1[2] = { b4l[1], b4l[3] };
                mma16816(acc[0], ah, bh0);
                mma16816(acc[0], ah, bl0);
                mma16816(acc[0], al, bh0);
                mma16816(acc[1], ah, bh1);
                mma16816(acc[1], ah, bl1);
                mma16816(acc[1], al, bh1);
            }

            // epilogue: add stash, activate -> sg
#pragma unroll
            for (int n8 = 0; n8 < 2; n8++) {
                int jl = n8 * 8 + tq * 2;
#pragma unroll
                for (int h = 0; h < 2; h++) {
                    int r = wm * 16 + lg + h * 8;
                    float vx = acc[n8][h * 2 + 0] + zpre[n8][h].x;
                    float vy = acc[n8][h * 2 + 1] + zpre[n8][h].y;
                    float2 rr;
                    if (wg == 2) { rr.x = tanhfast(vx); rr.y = tanhfast(vy); }
                    else         { rr.x = sigm(vx);     rr.y = sigm(vy);     }
                    *(float2*)&sg[(wg * 32 + r) * 18 + jl] = rr;
                }
            }
            __syncthreads();

            // elementwise update: 2 cells/thread
            {
                int cell = tid * 2;
                int r  = cell >> 4;
                int jl = cell & 15;
                float2 fv = *(const float2*)&sg[(0 * 32 + r) * 18 + jl];
                float2 iv = *(const float2*)&sg[(1 * 32 + r) * 18 + jl];
                float2 cv = *(const float2*)&sg[(2 * 32 + r) * 18 + jl];
                float2 ov = *(const float2*)&sg[(3 * 32 + r) * 18 + jl];
                float2 cold = *(const float2*)&cs[cell];
                float2 cnew, hnew;
                cnew.x = fv.x * cold.x + iv.x * cv.x;
                cnew.y = fv.y * cold.y + iv.y * cv.y;
                hnew.x = ov.x * tanhfast(cnew.x);
                hnew.y = ov.y * tanhfast(cnew.y);
                *(float2*)&cs[cell] = cnew;
                int mrow = t * BB + b0 + r;
                int jgl  = j0 + jl;
                *(float2*)&out[F_OFF + mrow * DLT + jgl] = fv;
                *(float2*)&out[I_OFF + mrow * DLT + jgl] = iv;
                *(float2*)&out[O_OFF + mrow * DLT + jgl] = ov;
                *(float2*)&out[C_OFF + (mrow + BB) * DLT + jgl] = cnew;
                *(float2*)&out[H_OFF + (mrow + BB) * DLT + jgl] = hnew;
            }

            // group barrier
            __syncthreads();
            if (tid == 0) {
                __threadfence();
                if (atomicAdd(&g_cnt2[slot], 1) == NGRP - 1) {
                    atomicExch(&g_cnt2[slot], 0);
                    red_release_add(&g_gen2[slot], 1);
                } else {
                    unsigned tgt = base_gen + 2 + t;
                    while (ld_acquire_gpu(&g_gen2[slot]) != tgt) { __nanosleep(32); }
                }
                __threadfence();
            }
            __syncthreads();
        }
    } else {
        // =================== phase1 role ===================
        __nv_bfloat16* AsH = (__nv_bfloat16*)(smem + AH_B);
        __nv_bfloat16* AsL = (__nv_bfloat16*)(smem + AL_B);
        __nv_bfloat16* BsH = (__nv_bfloat16*)(smem + BH_B);
        __nv_bfloat16* BsL = (__nv_bfloat16*)(smem + BL_B);

        const int p  = blockIdx.x - NPERSIST;
        const int bx = p & 7;
        const int by = p >> 3;
        const int g  = bx >> 1;
        const int j0 = (bx & 1) * 128;
        const int m0 = by * 128;

        const float* bias = (g == 0) ? b0v : (g == 1) ? b1v : (g == 2) ? b2v : b3v;

        const int wm = warp >> 1;     // 0..3
        const int wn = warp & 1;      // 0..1
        const int lg = lane >> 2;
        const int tq = lane & 3;

        const uint32_t aoff = shb + AH_B + ((wm * 32 + rowsel) * P1S + koff) * 2;
        const uint32_t boff = shb + BH_B + ((wn * 64 + rowsel) * P1S + koff) * 2;

        float acc[2][8][4];
#pragma unroll
        for (int i = 0; i < 2; i++)
#pragma unroll
            for (int j = 0; j < 8; j++)
#pragma unroll
                for (int u = 0; u < 4; u++) acc[i][j][u] = 0.0f;

        for (int c0 = 0; c0 < 256; c0 += 32) {
#pragma unroll
            for (int it = 0; it < 2; it++) {
                int idx = tid + it * 256;
                int row = idx >> 2;
                int q   = idx & 3;
                int off = (m0 + row) * 256 + c0 + q * 8;
                int sb  = row * P1S + q * 8;
                *(uint4*)&AsH[sb] = *(const uint4*)&g_Xhi[off];
                *(uint4*)&AsL[sb] = *(const uint4*)&g_Xlo[off];
            }
#pragma unroll
            for (int it = 0; it < 2; it++) {
                int idx = tid + it * 256;
                int row = idx >> 2;
                int q   = idx & 3;
                int off = g * 65536 + (j0 + row) * 256 + c0 + q * 8;
                int sb  = row * P1S + q * 8;
                *(uint4*)&BsH[sb] = *(const uint4*)&g_Wxhi[off];
                *(uint4*)&BsL[sb] = *(const uint4*)&g_Wxlo[off];
            }
            __syncthreads();

#pragma unroll
            for (int kk = 0; kk < 32; kk += 16) {
                uint32_t ah[2][4], al[2][4];
#pragma unroll
                for (int i = 0; i < 2; i++) {
                    ldsm4(ah[i], aoff + (i * 16 * P1S + kk) * 2);
                    ldsm4(al[i], aoff + (AL_B - AH_B) + (i * 16 * P1S + kk) * 2);
                }
#pragma unroll
                for (int jj = 0; jj < 4; jj++) {
                    uint32_t b4h[4], b4l[4];
                    ldsm4(b4h, boff + (jj * 16 * P1S + kk) * 2);
                    ldsm4(b4l, boff + (BL_B - BH_B) + (jj * 16 * P1S + kk) * 2);
                    uint32_t bh0[2] = { b4h[0], b4h[2] };
                    uint32_t bh1[2] = { b4h[1], b4h[3] };
                    uint32_t bl0[2] = { b4l[0], b4l[2] };
                    uint32_t bl1[2] = { b4l[1], b4l[3] };
#pragma unroll
                    for (int i = 0; i < 2; i++) {
                        mma16816(acc[i][jj * 2 + 0], ah[i], bh0);
                        mma16816(acc[i][jj * 2 + 0], ah[i], bl0);
                        mma16816(acc[i][jj * 2 + 0], al[i], bh0);
                        mma16816(acc[i][jj * 2 + 1], ah[i], bh1);
                        mma16816(acc[i][jj * 2 + 1], ah[i], bl1);
                        mma16816(acc[i][jj * 2 + 1], al[i], bh1);
                    }
                }
            }
            __syncthreads();
        }

        // epilogue: +bias, store pre-activations, then release t flag
#pragma unroll
        for (int i = 0; i < 2; i++) {
#pragma unroll
            for (int j = 0; j < 8; j++) {
                int col = j0 + wn * 64 + j * 8 + tq * 2;
                float bxv = bias[col], byv = bias[col + 1];
                int row0 = m0 + wm * 32 + i * 16 + lg;
#pragma unroll
                for (int h = 0; h < 2; h++) {
                    int m = row0 + h * 8;
                    float2 v;
                    v.x = acc[i][j][h * 2 + 0] + bxv;
                    v.y = acc[i][j][h * 2 + 1] + byv;
                    int idx;
                    if (g == 0)      idx = F_OFF + m * DLT + col;
                    else if (g == 1) idx = I_OFF + m * DLT + col;
                    else if (g == 2) idx = C_OFF + (m + BB) * DLT + col;
                    else             idx = O_OFF + m * DLT + col;
                    *(float2*)&out[idx] = v;
                }
            }
        }
        __syncthreads();
        if (tid == 0) {
            __threadfence();
            red_release_add(&t_done[by >> 1], 1);
        }
    }
}

// ---------------------------------------------------------------------------
extern "C" void kernel_launch(void* const* d_in, const int* in_sizes, int n_in,
                              void* d_out, int out_size)
{
    const float* X  = (const float*)d_in[0];
    const float* Wf = (const float*)d_in[1];
    const float* bf = (const float*)d_in[2];
    const float* Wi = (const float*)d_in[3];
    const float* bi = (const float*)d_in[4];
    const float* Wc = (const float*)d_in[5];
    const float* bc = (const float*)d_in[6];
    const float* Wo = (const float*)d_in[7];
    const float* bo = (const float*)d_in[8];
    float* out = (float*)d_out;

    cudaFuncSetAttribute(fused_kernel,
                         cudaFuncAttributeMaxDynamicSharedMemorySize, PSMEM);

    convX_kernel<<<TT * BB * DIN / 4 / 256, 256>>>(X);
    convW_kernel<<<256, 256>>>(Wf, Wi, Wc, Wo);
    fused_kernel<<<NPERSIST + 8192, 256, PSMEM>>>(Wf, Wi, Wc, Wo,
                                                  bf, bi, bc, bo, out);
}